// round 13
// baseline (speedup 1.0000x reference)
#include <cuda_runtime.h>
#include <math.h>

#define W 4096
#define S4 1024           // float4 per row
#define NKMAX 1024
#define SHARP 50.0f
#define MAXWIN 64
#define CGRID 256         // corr blocks
#define CK (NKMAX/CGRID)  // keys per corr block (4)

// ---------------- device scratch (no allocations allowed) ----------------
// All counters are MONOTONIC across graph replays (no reset kernel needed).
__device__ float2 g_mix[W];       // noisy_mix
__device__ float2 g_tw[W];        // twiddle table e^{i 2pi m / W}
__device__ float  g_corr[NKMAX];
__device__ unsigned g_t1;         // k_mix block ticket
__device__ unsigned g_md;         // mix-done epoch
__device__ unsigned g_tc;         // k_corr entry ticket (replay index)
__device__ unsigned g_t2;         // k_corr finish ticket (softmax election)
__device__ unsigned g_t3;         // k_out entry ticket (replay index)
__device__ unsigned g_done;       // softmax-done epoch
__device__ int    g_nwin;         // number of nonzero-attention winners
__device__ int    g_winn[MAXWIN]; // winner key indices (sorted ascending)
__device__ float  g_wina[MAXWIN]; // winner attention weights

// block-wide complex reduction (256 threads, 8 warps). Caller syncs before reuse.
__device__ __forceinline__ float2 block_reduce_c(float re, float im, float2* sred) {
#pragma unroll
    for (int off = 16; off; off >>= 1) {
        re += __shfl_xor_sync(0xffffffffu, re, off);
        im += __shfl_xor_sync(0xffffffffu, im, off);
    }
    int wid = threadIdx.x >> 5;
    if ((threadIdx.x & 31) == 0) sred[wid] = make_float2(re, im);
    __syncthreads();
    float2 acc = sred[0];
#pragma unroll
    for (int i = 1; i < 8; i++) { acc.x += sred[i].x; acc.y += sred[i].y; }
    return acc;
}

// ---------------- phase 1: noisy_mix[w] = sum_s holo*conj(cue) ----------------
// Triggers PDL at ENTRY so k_corr (and transitively k_out) can launch into
// slots freed during the last wave. Last-finishing block publishes g_md epoch.
__global__ __launch_bounds__(256) void k_mix(
    const float4* __restrict__ hr, const float4* __restrict__ hi,
    const float4* __restrict__ cr, const float4* __restrict__ ci)
{
    cudaTriggerProgrammaticLaunchCompletion();

    int row = blockIdx.x;
    int t   = threadIdx.x;
    if (row < 16) {   // side job: twiddle table
        int i = row * 256 + t;
        float s, c;
        sincospif((float)i * (1.0f / 2048.0f), &s, &c);  // i/2048 exact in fp32
        g_tw[i] = make_float2(c, s);
    }
    int base = row * S4;
    float re = 0.f, im = 0.f;
#pragma unroll
    for (int k = 0; k < 4; k++) {
        int i = base + t + k * 256;
        float4 a = hr[i];            // retain in L2 for k_out
        float4 b = hi[i];
        float4 c = __ldcs(&cr[i]);   // streaming
        float4 d = __ldcs(&ci[i]);
        re += a.x * c.x + b.x * d.x;  im += b.x * c.x - a.x * d.x;
        re += a.y * c.y + b.y * d.y;  im += b.y * c.y - a.y * d.y;
        re += a.z * c.z + b.z * d.z;  im += b.z * c.z - a.z * d.z;
        re += a.w * c.w + b.w * d.w;  im += b.w * c.w - a.w * d.w;
    }
    __shared__ float2 sred[8];
    float2 acc = block_reduce_c(re, im, sred);
    if (t == 0) g_mix[row] = acc;

    // publish: all stores (g_tw + g_mix) fenced, then ticket; 4096th block
    // of this replay bumps the mix-done epoch.
    __threadfence();
    __syncthreads();
    if (t == 0) {
        unsigned T = atomicAdd(&g_t1, 1u);
        if ((T & 4095u) == 4095u) atomicAdd(&g_md, 1u);
    }
}

// ------ phase 2: correlations (phasor recurrence) + last-block softmax ------
// Launches during k_mix's last wave; spins on g_md instead of grid-sync.
__global__ __launch_bounds__(256) void k_corr(const int* __restrict__ nkp) {
    cudaTriggerProgrammaticLaunchCompletion();   // release k_out's PDL launch

    int t   = threadIdx.x;
    int cid = blockIdx.x;

    // replay index + wait for this replay's mix epoch
    __shared__ unsigned sRep;
    if (t == 0) sRep = atomicAdd(&g_tc, 1u) >> 8;   // /CGRID
    __syncthreads();
    if (t == 0) {
        volatile unsigned* p = &g_md;
        while (*p <= sRep) __nanosleep(64);
    }
    __syncthreads();
    __threadfence();

    int nk = *nkp;
    __shared__ float2 sred[8];

    // key f: twiddle at w advances by rot = e^{i 2pi f*256/W} per 256-step chunk
    float tre[CK], tim[CK], rre[CK], rim[CK], are[CK], aim[CK];
#pragma unroll
    for (int kk = 0; kk < CK; kk++) {
        unsigned f = (unsigned)(cid * CK + kk) + 1u;
        float2 t0 = g_tw[(f * (unsigned)t) & 4095u];   // exact init
        float2 r0 = g_tw[(f << 8) & 4095u];            // exact rotation const
        tre[kk] = t0.x; tim[kk] = t0.y;
        rre[kk] = r0.x; rim[kk] = r0.y;
        are[kk] = 0.f;  aim[kk] = 0.f;
    }
#pragma unroll
    for (int ch = 0; ch < 16; ch++) {
        float2 m = __ldg(&g_mix[t + 256 * ch]);
#pragma unroll
        for (int kk = 0; kk < CK; kk++) {
            are[kk] += tre[kk] * m.x - tim[kk] * m.y;
            aim[kk] += tre[kk] * m.y + tim[kk] * m.x;
            float nr = tre[kk] * rre[kk] - tim[kk] * rim[kk];
            tim[kk]  = tre[kk] * rim[kk] + tim[kk] * rre[kk];
            tre[kk]  = nr;
        }
    }
#pragma unroll
    for (int kk = 0; kk < CK; kk++) {
        float2 acc = block_reduce_c(are[kk], aim[kk], sred);
        int n = cid * CK + kk;
        if (t == 0 && n < nk) g_corr[n] = sqrtf(acc.x * acc.x + acc.y * acc.y);
        __syncthreads();
    }
    __threadfence();

    // last-arriving block of this replay does softmax + winner compaction
    __shared__ unsigned sT2;
    if (t == 0) sT2 = atomicAdd(&g_t2, 1u);
    __syncthreads();
    if ((sT2 & (CGRID - 1u)) != (CGRID - 1u)) return;
    __threadfence();

    __shared__ float sredf[8];
    __shared__ float slog[NKMAX];
    __shared__ int   s_cnt;
    if (t == 0) s_cnt = 0;

    float l[4], mx = -INFINITY;
#pragma unroll
    for (int j = 0; j < 4; j++) {
        int n = t + 256 * j;
        float c = (n < nk) ? __ldcg(&g_corr[n]) : 0.f;
        l[j] = (n < nk) ? c * SHARP : -INFINITY;
        mx = fmaxf(mx, l[j]);
    }
#pragma unroll
    for (int off = 16; off; off >>= 1) mx = fmaxf(mx, __shfl_xor_sync(0xffffffffu, mx, off));
    if ((t & 31) == 0) sredf[t >> 5] = mx;
    __syncthreads();
    float bm = sredf[0];
#pragma unroll
    for (int i = 1; i < 8; i++) bm = fmaxf(bm, sredf[i]);
    __syncthreads();

    float e[4], s = 0.f;
#pragma unroll
    for (int j = 0; j < 4; j++) {
        int n = t + 256 * j;
        e[j] = (n < nk) ? expf(l[j] - bm) : 0.f;
        slog[t + 256 * j] = e[j];
        s += e[j];
    }
#pragma unroll
    for (int off = 16; off; off >>= 1) s += __shfl_xor_sync(0xffffffffu, s, off);
    if ((t & 31) == 0) sredf[t >> 5] = s;
    __syncthreads();
    float bs = sredf[0];
#pragma unroll
    for (int i = 1; i < 8; i++) bs += sredf[i];
    __syncthreads();

#pragma unroll
    for (int j = 0; j < 4; j++) {
        int n = t + 256 * j;
        float a = slog[n] / bs;
        if (a != 0.f && n < nk) {
            int slot = atomicAdd(&s_cnt, 1);
            if (slot < MAXWIN) { g_winn[slot] = n; g_wina[slot] = a; }
        }
    }
    __syncthreads();
    if (t == 0) {
        int m = s_cnt < MAXWIN ? s_cnt : MAXWIN;
        for (int i = 1; i < m; i++) {           // sort ascending by n
            int   kn = g_winn[i];
            float ka = g_wina[i];
            int j = i - 1;
            while (j >= 0 && g_winn[j] > kn) {
                g_winn[j + 1] = g_winn[j]; g_wina[j + 1] = g_wina[j]; j--;
            }
            g_winn[j + 1] = kn; g_wina[j + 1] = ka;
        }
        g_nwin = m;
        __threadfence();
        atomicAdd(&g_done, 1u);                 // publish epoch
    }
}

// ---------------- phase 3: out = holo * clean_key[:,None] ----------------
// Launches during k_mix tail / k_corr: prefetch full row into registers
// (reverse order -> L2-hot tail), spin on the softmax epoch, multiply, store.
__global__ __launch_bounds__(256) void k_out(
    const float4* __restrict__ hr, const float4* __restrict__ hi,
    float4* __restrict__ out)
{
    int t    = threadIdx.x;
    int row  = (W - 1) - blockIdx.x;            // reverse: hit L2-hot tail
    int base = row * S4;
    int i0 = base + t, i1 = i0 + 256, i2 = i0 + 512, i3 = i0 + 768;

    // prefetch entire row (overlaps mix tail + corr + softmax)
    float4 a0 = hr[i0], b0 = hi[i0];
    float4 a1 = hr[i1], b1 = hi[i1];
    float4 a2 = hr[i2], b2 = hi[i2];
    float4 a3 = hr[i3], b3 = hi[i3];

    // replay index + spin for this replay's softmax epoch
    __shared__ unsigned sR;
    if (t == 0) sR = atomicAdd(&g_t3, 1u) >> 12;    // / 4096 blocks per launch
    __syncthreads();
    unsigned rep = sR;
    if (t == 0) {
        volatile unsigned* p = &g_done;
        while (*p <= rep) __nanosleep(128);
    }
    __syncthreads();
    __threadfence();

    // clean_key[row] from compacted winners (one-hot in practice)
    int m = g_nwin;
    const float F = (float)(6.283185307179586 / 4096.0);  // fl(2*pi/W)
    float fw = (float)row;
    float ckre = 0.f, ckim = 0.f;
    for (int i = 0; i < m; i++) {
        int   n = g_winn[i];
        float a = g_wina[i];
        float freq = (float)(n + 1) * F;   // reference rounding order
        float ph   = freq * fw;
        float sn, cs;
        sincosf(ph, &sn, &cs);
        ckre = fmaf(a, cs, ckre);
        ckim = fmaf(a, sn, ckim);
    }

#define EMIT(ai, bi, idx)                                              \
    {                                                                  \
        float4 o0, o1;                                                 \
        o0.x = ai.x * ckre - bi.x * ckim;  o1.x = ai.x * ckim + bi.x * ckre; \
        o0.y = ai.y * ckre - bi.y * ckim;  o1.y = ai.y * ckim + bi.y * ckre; \
        o0.z = ai.z * ckre - bi.z * ckim;  o1.z = ai.z * ckim + bi.z * ckre; \
        o0.w = ai.w * ckre - bi.w * ckim;  o1.w = ai.w * ckim + bi.w * ckre; \
        __stcs(&out[idx],            o0);                              \
        __stcs(&out[idx + W * S4],   o1);                              \
    }
    EMIT(a0, b0, i0)
    EMIT(a1, b1, i1)
    EMIT(a2, b2, i2)
    EMIT(a3, b3, i3)
#undef EMIT
}

// ---------------- launcher ----------------
extern "C" void kernel_launch(void* const* d_in, const int* in_sizes, int n_in,
                              void* d_out, int out_size) {
    const float4* hr = (const float4*)d_in[0];
    const float4* hi = (const float4*)d_in[1];
    const float4* cr = (const float4*)d_in[2];
    const float4* ci = (const float4*)d_in[3];
    const int*    nk = (const int*)d_in[4];

    k_mix<<<W, 256>>>(hr, hi, cr, ci);

    cudaLaunchAttribute at[1];
    at[0].id = cudaLaunchAttributeProgrammaticStreamSerialization;
    at[0].val.programmaticStreamSerializationAllowed = 1;

    cudaLaunchConfig_t c1 = {};
    c1.gridDim  = dim3(CGRID);
    c1.blockDim = dim3(256);
    c1.stream   = 0;
    c1.attrs    = at;
    c1.numAttrs = 1;
    cudaLaunchKernelEx(&c1, k_corr, nk);

    cudaLaunchConfig_t c2 = {};
    c2.gridDim  = dim3(W);
    c2.blockDim = dim3(256);
    c2.stream   = 0;
    c2.attrs    = at;
    c2.numAttrs = 1;
    cudaLaunchKernelEx(&c2, k_out, hr, hi, (float4*)d_out);
}

// round 14
// speedup vs baseline: 1.0188x; 1.0188x over previous
#include <cuda_runtime.h>
#include <math.h>

#define W 4096
#define S4 1024           // float4 per row
#define NKMAX 1024
#define SHARP 50.0f
#define CGRID 512         // corr blocks
#define CK (NKMAX/CGRID)  // keys per corr block (2)

// ---------------- device scratch (no allocations allowed) ----------------
// All counters are MONOTONIC across graph replays (no reset kernel needed).
__device__ float2 g_mix[W];       // noisy_mix
__device__ float2 g_tw[W];        // twiddle table e^{i 2pi m / W}
__device__ float  g_corr[NKMAX];
__device__ unsigned g_cd;         // corr-blocks-done counter (monotonic)
__device__ unsigned g_t3;         // k_out entry ticket (replay index)

// block-wide complex reduction (256 threads, 8 warps). Caller syncs before reuse.
__device__ __forceinline__ float2 block_reduce_c(float re, float im, float2* sred) {
#pragma unroll
    for (int off = 16; off; off >>= 1) {
        re += __shfl_xor_sync(0xffffffffu, re, off);
        im += __shfl_xor_sync(0xffffffffu, im, off);
    }
    int wid = threadIdx.x >> 5;
    if ((threadIdx.x & 31) == 0) sred[wid] = make_float2(re, im);
    __syncthreads();
    float2 acc = sred[0];
#pragma unroll
    for (int i = 1; i < 8; i++) { acc.x += sred[i].x; acc.y += sred[i].y; }
    return acc;
}

// ---------------- phase 1: noisy_mix[w] = sum_s holo*conj(cue) ----------------
// R12 form: NO early trigger — nothing contends with this 81%-DRAM kernel.
__global__ __launch_bounds__(256) void k_mix(
    const float4* __restrict__ hr, const float4* __restrict__ hi,
    const float4* __restrict__ cr, const float4* __restrict__ ci)
{
    int row = blockIdx.x;
    int t   = threadIdx.x;
    if (row < 16) {   // side job: twiddle table
        int i = row * 256 + t;
        float s, c;
        sincospif((float)i * (1.0f / 2048.0f), &s, &c);  // i/2048 exact in fp32
        g_tw[i] = make_float2(c, s);
    }
    int base = row * S4;
    float re = 0.f, im = 0.f;
#pragma unroll
    for (int k = 0; k < 4; k++) {
        int i = base + t + k * 256;
        float4 a = hr[i];            // retain in L2 for k_out
        float4 b = hi[i];
        float4 c = __ldcs(&cr[i]);   // streaming
        float4 d = __ldcs(&ci[i]);
        re += a.x * c.x + b.x * d.x;  im += b.x * c.x - a.x * d.x;
        re += a.y * c.y + b.y * d.y;  im += b.y * c.y - a.y * d.y;
        re += a.z * c.z + b.z * d.z;  im += b.z * c.z - a.z * d.z;
        re += a.w * c.w + b.w * d.w;  im += b.w * c.w - a.w * d.w;
    }
    __shared__ float2 sred[8];
    float2 acc = block_reduce_c(re, im, sred);
    if (t == 0) g_mix[row] = acc;
}

// ------ phase 2: correlations only (phasor recurrence); counter publish ------
__global__ __launch_bounds__(256) void k_corr(const int* __restrict__ nkp) {
    cudaTriggerProgrammaticLaunchCompletion();   // release k_out's PDL launch
    cudaGridDependencySynchronize();             // wait for k_mix completion

    int t   = threadIdx.x;
    int cid = blockIdx.x;
    int nk  = *nkp;
    __shared__ float2 sred[8];

    // key f: twiddle at w advances by rot = e^{i 2pi f*256/W} per 256-step chunk
    float tre[CK], tim[CK], rre[CK], rim[CK], are[CK], aim[CK];
#pragma unroll
    for (int kk = 0; kk < CK; kk++) {
        unsigned f = (unsigned)(cid * CK + kk) + 1u;
        float2 t0 = g_tw[(f * (unsigned)t) & 4095u];   // exact init
        float2 r0 = g_tw[(f << 8) & 4095u];            // exact rotation const
        tre[kk] = t0.x; tim[kk] = t0.y;
        rre[kk] = r0.x; rim[kk] = r0.y;
        are[kk] = 0.f;  aim[kk] = 0.f;
    }
#pragma unroll
    for (int ch = 0; ch < 16; ch++) {
        float2 m = __ldg(&g_mix[t + 256 * ch]);
#pragma unroll
        for (int kk = 0; kk < CK; kk++) {
            are[kk] += tre[kk] * m.x - tim[kk] * m.y;
            aim[kk] += tre[kk] * m.y + tim[kk] * m.x;
            float nr = tre[kk] * rre[kk] - tim[kk] * rim[kk];
            tim[kk]  = tre[kk] * rim[kk] + tim[kk] * rre[kk];
            tre[kk]  = nr;
        }
    }
#pragma unroll
    for (int kk = 0; kk < CK; kk++) {
        float2 acc = block_reduce_c(are[kk], aim[kk], sred);
        int n = cid * CK + kk;
        if (t == 0 && n < nk) g_corr[n] = sqrtf(acc.x * acc.x + acc.y * acc.y);
        __syncthreads();   // sred reuse guard
    }
    __threadfence();
    if (t == 0) atomicAdd(&g_cd, 1u);            // publish this block's keys
}

// ---------------- phase 3: softmax (redundant per block) + out ----------------
// PDL-launched during k_corr: prefetch full row, wait for all corr blocks of
// this replay, compute softmax locally, derive clean_key[row], multiply, store.
__global__ __launch_bounds__(256) void k_out(
    const float4* __restrict__ hr, const float4* __restrict__ hi,
    float4* __restrict__ out, const int* __restrict__ nkp)
{
    int t    = threadIdx.x;
    int row  = (W - 1) - blockIdx.x;            // reverse: hit L2-hot tail
    int base = row * S4;
    int i0 = base + t, i1 = i0 + 256, i2 = i0 + 512, i3 = i0 + 768;

    // prefetch entire row (overlaps corr under PDL)
    float4 a0 = hr[i0], b0 = hi[i0];
    float4 a1 = hr[i1], b1 = hi[i1];
    float4 a2 = hr[i2], b2 = hi[i2];
    float4 a3 = hr[i3], b3 = hi[i3];

    // replay index + wait until all CGRID corr blocks of this replay published
    __shared__ unsigned sR;
    if (t == 0) sR = atomicAdd(&g_t3, 1u) >> 12;    // / 4096 blocks per launch
    __syncthreads();
    unsigned need = (sR + 1u) * CGRID;
    if (t == 0) {
        volatile unsigned* p = &g_cd;
        while (*p < need) __nanosleep(64);
    }
    __syncthreads();
    __threadfence();

    int nk = *nkp;

    // ---- redundant softmax over g_corr (L2-hot) ----
    __shared__ float sredf[8];
    float l[4], mx = -INFINITY;
#pragma unroll
    for (int j = 0; j < 4; j++) {
        int n = t + 256 * j;
        float c = (n < nk) ? __ldg(&g_corr[n]) : 0.f;
        l[j] = (n < nk) ? c * SHARP : -INFINITY;
        mx = fmaxf(mx, l[j]);
    }
#pragma unroll
    for (int off = 16; off; off >>= 1) mx = fmaxf(mx, __shfl_xor_sync(0xffffffffu, mx, off));
    if ((t & 31) == 0) sredf[t >> 5] = mx;
    __syncthreads();
    float bm = sredf[0];
#pragma unroll
    for (int i = 1; i < 8; i++) bm = fmaxf(bm, sredf[i]);
    __syncthreads();

    float e[4], s = 0.f;
#pragma unroll
    for (int j = 0; j < 4; j++) {
        int n = t + 256 * j;
        e[j] = (n < nk) ? expf(l[j] - bm) : 0.f;
        s += e[j];
    }
#pragma unroll
    for (int off = 16; off; off >>= 1) s += __shfl_xor_sync(0xffffffffu, s, off);
    if ((t & 31) == 0) sredf[t >> 5] = s;
    __syncthreads();
    float bs = sredf[0];
#pragma unroll
    for (int i = 1; i < 8; i++) bs += sredf[i];
    __syncthreads();

    // ---- clean_key[row]: per-thread winner contributions, block-reduced ----
    // (one-hot in practice: ~1 thread executes 1 sincosf)
    const float F = (float)(6.283185307179586 / 4096.0);  // fl(2*pi/W)
    float fw = (float)row;
    float ckre = 0.f, ckim = 0.f;
#pragma unroll
    for (int j = 0; j < 4; j++) {
        int n = t + 256 * j;
        float a = e[j] / bs;
        if (a != 0.f && n < nk) {
            float freq = (float)(n + 1) * F;   // reference rounding order
            float ph   = freq * fw;
            float sn, cs;
            sincosf(ph, &sn, &cs);
            ckre = fmaf(a, cs, ckre);
            ckim = fmaf(a, sn, ckim);
        }
    }
    __shared__ float2 sred[8];
    float2 ck = block_reduce_c(ckre, ckim, sred);
    float cre = ck.x, cim = ck.y;

#define EMIT(ai, bi, idx)                                              \
    {                                                                  \
        float4 o0, o1;                                                 \
        o0.x = ai.x * cre - bi.x * cim;  o1.x = ai.x * cim + bi.x * cre; \
        o0.y = ai.y * cre - bi.y * cim;  o1.y = ai.y * cim + bi.y * cre; \
        o0.z = ai.z * cre - bi.z * cim;  o1.z = ai.z * cim + bi.z * cre; \
        o0.w = ai.w * cre - bi.w * cim;  o1.w = ai.w * cim + bi.w * cre; \
        __stcs(&out[idx],            o0);                              \
        __stcs(&out[idx + W * S4],   o1);                              \
    }
    EMIT(a0, b0, i0)
    EMIT(a1, b1, i1)
    EMIT(a2, b2, i2)
    EMIT(a3, b3, i3)
#undef EMIT
}

// ---------------- launcher ----------------
extern "C" void kernel_launch(void* const* d_in, const int* in_sizes, int n_in,
                              void* d_out, int out_size) {
    const float4* hr = (const float4*)d_in[0];
    const float4* hi = (const float4*)d_in[1];
    const float4* cr = (const float4*)d_in[2];
    const float4* ci = (const float4*)d_in[3];
    const int*    nk = (const int*)d_in[4];

    k_mix<<<W, 256>>>(hr, hi, cr, ci);

    cudaLaunchAttribute at[1];
    at[0].id = cudaLaunchAttributeProgrammaticStreamSerialization;
    at[0].val.programmaticStreamSerializationAllowed = 1;

    cudaLaunchConfig_t c1 = {};
    c1.gridDim  = dim3(CGRID);
    c1.blockDim = dim3(256);
    c1.stream   = 0;
    c1.attrs    = at;
    c1.numAttrs = 1;
    cudaLaunchKernelEx(&c1, k_corr, nk);

    cudaLaunchConfig_t c2 = {};
    c2.gridDim  = dim3(W);
    c2.blockDim = dim3(256);
    c2.stream   = 0;
    c2.attrs    = at;
    c2.numAttrs = 1;
    cudaLaunchKernelEx(&c2, k_out, hr, hi, (float4*)d_out, nk);
}

// round 15
// speedup vs baseline: 1.0839x; 1.0639x over previous
#include <cuda_runtime.h>
#include <math.h>

#define W 4096
#define S4 1024           // float4 per row
#define NKMAX 1024
#define SHARP 50.0f
#define MAXWIN 64
#define CGRID 512         // corr blocks (subset of k_fused's grid)
#define CK (NKMAX/CGRID)  // keys per corr block (2)

// ---------------- device scratch (no allocations allowed) ----------------
// All counters are MONOTONIC across graph replays (no reset kernel needed).
__device__ float2 g_mix[W];       // noisy_mix
__device__ float2 g_tw[W];        // twiddle table e^{i 2pi m / W}
__device__ float  g_corr[NKMAX];
__device__ unsigned g_cd;         // corr-blocks-done counter (election)
__device__ unsigned g_t3;         // k_fused entry ticket (replay index)
__device__ unsigned g_done;       // softmax-done epoch
__device__ int    g_nwin;         // number of nonzero-attention winners
__device__ int    g_winn[MAXWIN]; // winner key indices (sorted ascending)
__device__ float  g_wina[MAXWIN]; // winner attention weights

// block-wide complex reduction (256 threads, 8 warps). Caller syncs before reuse.
__device__ __forceinline__ float2 block_reduce_c(float re, float im, float2* sred) {
#pragma unroll
    for (int off = 16; off; off >>= 1) {
        re += __shfl_xor_sync(0xffffffffu, re, off);
        im += __shfl_xor_sync(0xffffffffu, im, off);
    }
    int wid = threadIdx.x >> 5;
    if ((threadIdx.x & 31) == 0) sred[wid] = make_float2(re, im);
    __syncthreads();
    float2 acc = sred[0];
#pragma unroll
    for (int i = 1; i < 8; i++) { acc.x += sred[i].x; acc.y += sred[i].y; }
    return acc;
}

// ---------------- phase 1: noisy_mix[w] = sum_s holo*conj(cue) ----------------
// Pure R12 form: nothing overlaps this 81%-DRAM kernel.
__global__ __launch_bounds__(256) void k_mix(
    const float4* __restrict__ hr, const float4* __restrict__ hi,
    const float4* __restrict__ cr, const float4* __restrict__ ci)
{
    int row = blockIdx.x;
    int t   = threadIdx.x;
    if (row < 16) {   // side job: twiddle table
        int i = row * 256 + t;
        float s, c;
        sincospif((float)i * (1.0f / 2048.0f), &s, &c);  // i/2048 exact in fp32
        g_tw[i] = make_float2(c, s);
    }
    int base = row * S4;
    float re = 0.f, im = 0.f;
#pragma unroll
    for (int k = 0; k < 4; k++) {
        int i = base + t + k * 256;
        float4 a = hr[i];            // retain in L2 for k_fused
        float4 b = hi[i];
        float4 c = __ldcs(&cr[i]);   // streaming
        float4 d = __ldcs(&ci[i]);
        re += a.x * c.x + b.x * d.x;  im += b.x * c.x - a.x * d.x;
        re += a.y * c.y + b.y * d.y;  im += b.y * c.y - a.y * d.y;
        re += a.z * c.z + b.z * d.z;  im += b.z * c.z - a.z * d.z;
        re += a.w * c.w + b.w * d.w;  im += b.w * c.w - a.w * d.w;
    }
    __shared__ float2 sred[8];
    float2 acc = block_reduce_c(re, im, sred);
    if (t == 0) g_mix[row] = acc;
}

// ====== phase 2+3 fused: corr (blocks 0..511) + softmax (electee) + out ======
__global__ __launch_bounds__(256) void k_fused(
    const float4* __restrict__ hr, const float4* __restrict__ hi,
    float4* __restrict__ out, const int* __restrict__ nkp)
{
    int t   = threadIdx.x;
    int bid = blockIdx.x;
    int row = (W - 1) - bid;          // reverse: hit L2-hot tail of k_mix
    int base = row * S4;
    int i0 = base + t, i1 = i0 + 256, i2 = i0 + 512, i3 = i0 + 768;
    __shared__ float2 sred[8];

    // replay index (monotonic ticket)
    __shared__ unsigned sR;
    if (t == 0) sR = atomicAdd(&g_t3, 1u) >> 12;   // / 4096 blocks per launch
    __syncthreads();
    unsigned rep = sR;

    int nk = *nkp;

    float4 a0, b0, a1, b1, a2, b2, a3, b3;
    bool is_corr = (bid < CGRID);

    if (is_corr) {
        // ---- correlations for CK keys via register phasor recurrence ----
        // key f: twiddle at w advances by rot = e^{i 2pi f*256/W} per chunk
        float tre[CK], tim[CK], rre[CK], rim[CK], are[CK], aim[CK];
#pragma unroll
        for (int kk = 0; kk < CK; kk++) {
            unsigned f = (unsigned)(bid * CK + kk) + 1u;
            float2 t0 = g_tw[(f * (unsigned)t) & 4095u];   // exact init
            float2 r0 = g_tw[(f << 8) & 4095u];            // exact rotation
            tre[kk] = t0.x; tim[kk] = t0.y;
            rre[kk] = r0.x; rim[kk] = r0.y;
            are[kk] = 0.f;  aim[kk] = 0.f;
        }
#pragma unroll
        for (int ch = 0; ch < 16; ch++) {
            float2 m = __ldg(&g_mix[t + 256 * ch]);
#pragma unroll
            for (int kk = 0; kk < CK; kk++) {
                are[kk] += tre[kk] * m.x - tim[kk] * m.y;
                aim[kk] += tre[kk] * m.y + tim[kk] * m.x;
                float nr = tre[kk] * rre[kk] - tim[kk] * rim[kk];
                tim[kk]  = tre[kk] * rim[kk] + tim[kk] * rre[kk];
                tre[kk]  = nr;
            }
        }
#pragma unroll
        for (int kk = 0; kk < CK; kk++) {
            float2 acc = block_reduce_c(are[kk], aim[kk], sred);
            int n = bid * CK + kk;
            if (t == 0 && n < nk) g_corr[n] = sqrtf(acc.x * acc.x + acc.y * acc.y);
            __syncthreads();   // sred reuse guard
        }
        __threadfence();

        // election: the CGRID-th finisher of this replay does the softmax
        __shared__ unsigned sT;
        if (t == 0) sT = atomicAdd(&g_cd, 1u);
        __syncthreads();
        if ((sT & (CGRID - 1u)) == (CGRID - 1u)) {
            __threadfence();
            __shared__ float sredf[8];
            __shared__ float slog[NKMAX];
            __shared__ int   s_cnt;
            if (t == 0) s_cnt = 0;

            float l[4], mx = -INFINITY;
#pragma unroll
            for (int j = 0; j < 4; j++) {
                int n = t + 256 * j;
                float c = (n < nk) ? __ldcg(&g_corr[n]) : 0.f;
                l[j] = (n < nk) ? c * SHARP : -INFINITY;
                mx = fmaxf(mx, l[j]);
            }
#pragma unroll
            for (int off = 16; off; off >>= 1) mx = fmaxf(mx, __shfl_xor_sync(0xffffffffu, mx, off));
            if ((t & 31) == 0) sredf[t >> 5] = mx;
            __syncthreads();
            float bm = sredf[0];
#pragma unroll
            for (int i = 1; i < 8; i++) bm = fmaxf(bm, sredf[i]);
            __syncthreads();

            float e[4], s = 0.f;
#pragma unroll
            for (int j = 0; j < 4; j++) {
                int n = t + 256 * j;
                e[j] = (n < nk) ? expf(l[j] - bm) : 0.f;
                slog[t + 256 * j] = e[j];
                s += e[j];
            }
#pragma unroll
            for (int off = 16; off; off >>= 1) s += __shfl_xor_sync(0xffffffffu, s, off);
            if ((t & 31) == 0) sredf[t >> 5] = s;
            __syncthreads();
            float bs = sredf[0];
#pragma unroll
            for (int i = 1; i < 8; i++) bs += sredf[i];
            __syncthreads();

#pragma unroll
            for (int j = 0; j < 4; j++) {
                int n = t + 256 * j;
                float a = slog[n] / bs;
                if (a != 0.f && n < nk) {
                    int slot = atomicAdd(&s_cnt, 1);
                    if (slot < MAXWIN) { g_winn[slot] = n; g_wina[slot] = a; }
                }
            }
            __syncthreads();
            if (t == 0) {
                int m = s_cnt < MAXWIN ? s_cnt : MAXWIN;
                for (int i = 1; i < m; i++) {      // sort ascending by n
                    int   kn = g_winn[i];
                    float ka = g_wina[i];
                    int j = i - 1;
                    while (j >= 0 && g_winn[j] > kn) {
                        g_winn[j + 1] = g_winn[j]; g_wina[j + 1] = g_wina[j]; j--;
                    }
                    g_winn[j + 1] = kn; g_wina[j + 1] = ka;
                }
                g_nwin = m;
                __threadfence();
                atomicAdd(&g_done, 1u);            // publish epoch
            }
        }
    } else {
        // ---- non-corr blocks: prefetch full row (overlaps corr) ----
        a0 = hr[i0]; b0 = hi[i0];
        a1 = hr[i1]; b1 = hi[i1];
        a2 = hr[i2]; b2 = hi[i2];
        a3 = hr[i3]; b3 = hi[i3];
    }

    // ---- wait for this replay's softmax epoch ----
    if (t == 0) {
        volatile unsigned* p = &g_done;
        while (*p <= rep) __nanosleep(64);
    }
    __syncthreads();
    __threadfence();

    if (is_corr) {   // corr blocks load their (L2-hot) row now
        a0 = hr[i0]; b0 = hi[i0];
        a1 = hr[i1]; b1 = hi[i1];
        a2 = hr[i2]; b2 = hi[i2];
        a3 = hr[i3]; b3 = hi[i3];
    }

    // clean_key[row] from compacted winners (one-hot in practice)
    int m = g_nwin;
    const float F = (float)(6.283185307179586 / 4096.0);  // fl(2*pi/W)
    float fw = (float)row;
    float ckre = 0.f, ckim = 0.f;
    for (int i = 0; i < m; i++) {
        int   n = g_winn[i];
        float a = g_wina[i];
        float freq = (float)(n + 1) * F;   // reference rounding order
        float ph   = freq * fw;
        float sn, cs;
        sincosf(ph, &sn, &cs);
        ckre = fmaf(a, cs, ckre);
        ckim = fmaf(a, sn, ckim);
    }

#define EMIT(ai, bi, idx)                                              \
    {                                                                  \
        float4 o0, o1;                                                 \
        o0.x = ai.x * ckre - bi.x * ckim;  o1.x = ai.x * ckim + bi.x * ckre; \
        o0.y = ai.y * ckre - bi.y * ckim;  o1.y = ai.y * ckim + bi.y * ckre; \
        o0.z = ai.z * ckre - bi.z * ckim;  o1.z = ai.z * ckim + bi.z * ckre; \
        o0.w = ai.w * ckre - bi.w * ckim;  o1.w = ai.w * ckim + bi.w * ckre; \
        __stcs(&out[idx],            o0);                              \
        __stcs(&out[idx + W * S4],   o1);                              \
    }
    EMIT(a0, b0, i0)
    EMIT(a1, b1, i1)
    EMIT(a2, b2, i2)
    EMIT(a3, b3, i3)
#undef EMIT
}

// ---------------- launcher ----------------
extern "C" void kernel_launch(void* const* d_in, const int* in_sizes, int n_in,
                              void* d_out, int out_size) {
    const float4* hr = (const float4*)d_in[0];
    const float4* hi = (const float4*)d_in[1];
    const float4* cr = (const float4*)d_in[2];
    const float4* ci = (const float4*)d_in[3];
    const int*    nk = (const int*)d_in[4];

    k_mix  <<<W, 256>>>(hr, hi, cr, ci);
    k_fused<<<W, 256>>>(hr, hi, (float4*)d_out, nk);
}

// round 16
// speedup vs baseline: 1.1143x; 1.0280x over previous
#include <cuda_runtime.h>
#include <math.h>

#define W 4096
#define S4 1024           // float4 per row
#define NKMAX 1024
#define SHARP 50.0f
#define MAXWIN 64
#define CGRID 512         // corr blocks (subset of k_fused's grid)
#define CK (NKMAX/CGRID)  // keys per corr block (2)

// ---------------- device scratch (no allocations allowed) ----------------
// All counters are MONOTONIC across graph replays (no reset kernel needed).
__device__ float2 g_mix[W];       // noisy_mix
__device__ float2 g_tw[W];        // twiddle table e^{i 2pi m / W}
__device__ float  g_corr[NKMAX];
__device__ unsigned g_cd;         // corr-blocks-done counter (election)
__device__ unsigned g_t3;         // k_fused entry ticket (replay index)
__device__ unsigned g_done;       // softmax-done epoch
__device__ int    g_nwin;         // number of nonzero-attention winners
__device__ int    g_winn[MAXWIN]; // winner key indices (sorted ascending)
__device__ float  g_wina[MAXWIN]; // winner attention weights

// block-wide complex reduction (256 threads, 8 warps). Caller syncs before reuse.
__device__ __forceinline__ float2 block_reduce_c(float re, float im, float2* sred) {
#pragma unroll
    for (int off = 16; off; off >>= 1) {
        re += __shfl_xor_sync(0xffffffffu, re, off);
        im += __shfl_xor_sync(0xffffffffu, im, off);
    }
    int wid = threadIdx.x >> 5;
    if ((threadIdx.x & 31) == 0) sred[wid] = make_float2(re, im);
    __syncthreads();
    float2 acc = sred[0];
#pragma unroll
    for (int i = 1; i < 8; i++) { acc.x += sred[i].x; acc.y += sred[i].y; }
    return acc;
}

// ---------------- phase 1: noisy_mix[w] = sum_s holo*conj(cue) ----------------
// Pure R12 form: nothing overlaps this 81%-DRAM kernel.
__global__ __launch_bounds__(256) void k_mix(
    const float4* __restrict__ hr, const float4* __restrict__ hi,
    const float4* __restrict__ cr, const float4* __restrict__ ci)
{
    int row = blockIdx.x;
    int t   = threadIdx.x;
    if (row < 16) {   // side job: twiddle table
        int i = row * 256 + t;
        float s, c;
        sincospif((float)i * (1.0f / 2048.0f), &s, &c);  // i/2048 exact in fp32
        g_tw[i] = make_float2(c, s);
    }
    int base = row * S4;
    float re = 0.f, im = 0.f;
#pragma unroll
    for (int k = 0; k < 4; k++) {
        int i = base + t + k * 256;
        float4 a = hr[i];            // retain in L2 for k_fused
        float4 b = hi[i];
        float4 c = __ldcs(&cr[i]);   // streaming
        float4 d = __ldcs(&ci[i]);
        re += a.x * c.x + b.x * d.x;  im += b.x * c.x - a.x * d.x;
        re += a.y * c.y + b.y * d.y;  im += b.y * c.y - a.y * d.y;
        re += a.z * c.z + b.z * d.z;  im += b.z * c.z - a.z * d.z;
        re += a.w * c.w + b.w * d.w;  im += b.w * c.w - a.w * d.w;
    }
    __shared__ float2 sred[8];
    float2 acc = block_reduce_c(re, im, sred);
    if (t == 0) g_mix[row] = acc;
}

// ====== phase 2+3 fused: corr (blocks 0..511) + softmax (electee) + out ======
// Register-lean: only one chunk prefetched across the epoch wait; occupancy 6/SM.
__global__ __launch_bounds__(256, 6) void k_fused(
    const float4* __restrict__ hr, const float4* __restrict__ hi,
    float4* __restrict__ out, const int* __restrict__ nkp)
{
    int t   = threadIdx.x;
    int bid = blockIdx.x;
    int row = (W - 1) - bid;          // reverse: hit L2-hot tail of k_mix
    int base = row * S4;
    int i0 = base + t;
    __shared__ float2 sred[8];

    // replay index (monotonic ticket)
    __shared__ unsigned sR;
    if (t == 0) sR = atomicAdd(&g_t3, 1u) >> 12;   // / 4096 blocks per launch
    __syncthreads();
    unsigned rep = sR;

    int nk = *nkp;
    bool is_corr = (bid < CGRID);
    float4 a0, b0;

    if (is_corr) {
        // ---- correlations for CK keys via register phasor recurrence ----
        float tre[CK], tim[CK], rre[CK], rim[CK], are[CK], aim[CK];
#pragma unroll
        for (int kk = 0; kk < CK; kk++) {
            unsigned f = (unsigned)(bid * CK + kk) + 1u;
            float2 t0 = g_tw[(f * (unsigned)t) & 4095u];   // exact init
            float2 r0 = g_tw[(f << 8) & 4095u];            // exact rotation
            tre[kk] = t0.x; tim[kk] = t0.y;
            rre[kk] = r0.x; rim[kk] = r0.y;
            are[kk] = 0.f;  aim[kk] = 0.f;
        }
#pragma unroll
        for (int ch = 0; ch < 16; ch++) {
            float2 m = __ldg(&g_mix[t + 256 * ch]);
#pragma unroll
            for (int kk = 0; kk < CK; kk++) {
                are[kk] += tre[kk] * m.x - tim[kk] * m.y;
                aim[kk] += tre[kk] * m.y + tim[kk] * m.x;
                float nr = tre[kk] * rre[kk] - tim[kk] * rim[kk];
                tim[kk]  = tre[kk] * rim[kk] + tim[kk] * rre[kk];
                tre[kk]  = nr;
            }
        }
#pragma unroll
        for (int kk = 0; kk < CK; kk++) {
            float2 acc = block_reduce_c(are[kk], aim[kk], sred);
            int n = bid * CK + kk;
            if (t == 0 && n < nk) g_corr[n] = sqrtf(acc.x * acc.x + acc.y * acc.y);
            __syncthreads();   // sred reuse guard
        }
        __threadfence();

        // election: the CGRID-th finisher of this replay does the softmax
        __shared__ unsigned sT;
        if (t == 0) sT = atomicAdd(&g_cd, 1u);
        __syncthreads();
        if ((sT & (CGRID - 1u)) == (CGRID - 1u)) {
            __threadfence();
            __shared__ float sredf[8];
            __shared__ float slog[NKMAX];
            __shared__ int   s_cnt;
            if (t == 0) s_cnt = 0;

            float l[4], mx = -INFINITY;
#pragma unroll
            for (int j = 0; j < 4; j++) {
                int n = t + 256 * j;
                float c = (n < nk) ? __ldcg(&g_corr[n]) : 0.f;
                l[j] = (n < nk) ? c * SHARP : -INFINITY;
                mx = fmaxf(mx, l[j]);
            }
#pragma unroll
            for (int off = 16; off; off >>= 1) mx = fmaxf(mx, __shfl_xor_sync(0xffffffffu, mx, off));
            if ((t & 31) == 0) sredf[t >> 5] = mx;
            __syncthreads();
            float bm = sredf[0];
#pragma unroll
            for (int i = 1; i < 8; i++) bm = fmaxf(bm, sredf[i]);
            __syncthreads();

            float e[4], s = 0.f;
#pragma unroll
            for (int j = 0; j < 4; j++) {
                int n = t + 256 * j;
                e[j] = (n < nk) ? expf(l[j] - bm) : 0.f;
                slog[t + 256 * j] = e[j];
                s += e[j];
            }
#pragma unroll
            for (int off = 16; off; off >>= 1) s += __shfl_xor_sync(0xffffffffu, s, off);
            if ((t & 31) == 0) sredf[t >> 5] = s;
            __syncthreads();
            float bs = sredf[0];
#pragma unroll
            for (int i = 1; i < 8; i++) bs += sredf[i];
            __syncthreads();

#pragma unroll
            for (int j = 0; j < 4; j++) {
                int n = t + 256 * j;
                float a = slog[n] / bs;
                if (a != 0.f && n < nk) {
                    int slot = atomicAdd(&s_cnt, 1);
                    if (slot < MAXWIN) { g_winn[slot] = n; g_wina[slot] = a; }
                }
            }
            __syncthreads();
            if (t == 0) {
                int m = s_cnt < MAXWIN ? s_cnt : MAXWIN;
                for (int i = 1; i < m; i++) {      // sort ascending by n
                    int   kn = g_winn[i];
                    float ka = g_wina[i];
                    int j = i - 1;
                    while (j >= 0 && g_winn[j] > kn) {
                        g_winn[j + 1] = g_winn[j]; g_wina[j + 1] = g_wina[j]; j--;
                    }
                    g_winn[j + 1] = kn; g_wina[j + 1] = ka;
                }
                g_nwin = m;
                __threadfence();
                atomicAdd(&g_done, 1u);            // publish epoch
            }
        }
    } else {
        // non-corr blocks: prefetch ONE chunk only (8 regs live across wait)
        a0 = hr[i0]; b0 = hi[i0];
    }

    // ---- wait for this replay's softmax epoch ----
    if (t == 0) {
        volatile unsigned* p = &g_done;
        while (*p <= rep) __nanosleep(64);
    }
    __syncthreads();
    __threadfence();

    if (is_corr) { a0 = hr[i0]; b0 = hi[i0]; }   // corr blocks load now

    // clean_key[row] from compacted winners (one-hot in practice)
    int m = g_nwin;
    const float F = (float)(6.283185307179586 / 4096.0);  // fl(2*pi/W)
    float fw = (float)row;
    float ckre = 0.f, ckim = 0.f;
    for (int i = 0; i < m; i++) {
        int   n = g_winn[i];
        float a = g_wina[i];
        float freq = (float)(n + 1) * F;   // reference rounding order
        float ph   = freq * fw;
        float sn, cs;
        sincosf(ph, &sn, &cs);
        ckre = fmaf(a, cs, ckre);
        ckim = fmaf(a, sn, ckim);
    }

#define EMIT(ai, bi, idx)                                              \
    {                                                                  \
        float4 o0, o1;                                                 \
        o0.x = ai.x * ckre - bi.x * ckim;  o1.x = ai.x * ckim + bi.x * ckre; \
        o0.y = ai.y * ckre - bi.y * ckim;  o1.y = ai.y * ckim + bi.y * ckre; \
        o0.z = ai.z * ckre - bi.z * ckim;  o1.z = ai.z * ckim + bi.z * ckre; \
        o0.w = ai.w * ckre - bi.w * ckim;  o1.w = ai.w * ckim + bi.w * ckre; \
        __stcs(&out[idx],            o0);                              \
        __stcs(&out[idx + W * S4],   o1);                              \
    }
    // chunk 0 (prefetched), then stream chunks 1..3
    EMIT(a0, b0, i0)
#pragma unroll
    for (int k = 1; k < 4; k++) {
        int i = i0 + k * 256;
        float4 a = hr[i], b = hi[i];
        EMIT(a, b, i)
    }
#undef EMIT
}

// ---------------- launcher ----------------
extern "C" void kernel_launch(void* const* d_in, const int* in_sizes, int n_in,
                              void* d_out, int out_size) {
    const float4* hr = (const float4*)d_in[0];
    const float4* hi = (const float4*)d_in[1];
    const float4* cr = (const float4*)d_in[2];
    const float4* ci = (const float4*)d_in[3];
    const int*    nk = (const int*)d_in[4];

    k_mix  <<<W, 256>>>(hr, hi, cr, ci);
    k_fused<<<W, 256>>>(hr, hi, (float4*)d_out, nk);
}